// round 5
// baseline (speedup 1.0000x reference)
#include <cuda_runtime.h>
#include <cuda_bf16.h>
#include <math.h>
#include <stdint.h>

#define F_DIM 256
#define N_MAX 200000
#define B_MAX 4000

// ---- scratch (device globals: allocation-free) ----
__device__ float g_kq[B_MAX * F_DIM];
__device__ float g_kb[B_MAX];
__device__ float g_vmol[B_MAX * F_DIM];
__device__ float g_a[N_MAX];
__device__ float g_part[(N_MAX + 7) / 8];
__device__ float g_inv[1];
__device__ float g_H[(size_t)N_MAX * F_DIM];
__device__ __nv_bfloat16 g_Whi[5 * F_DIM * F_DIM];
__device__ __nv_bfloat16 g_Wlo[5 * F_DIM * F_DIM];

// ============================================================
// helpers
// ============================================================
__device__ __forceinline__ uint32_t smem_u32(const void* p) {
    uint32_t a;
    asm("{ .reg .u64 t; cvta.to.shared.u64 t, %1; cvt.u32.u64 %0, t; }" : "=r"(a) : "l"(p));
    return a;
}
#define LDSM_X4(r, addr) \
    asm volatile("ldmatrix.sync.aligned.m8n8.x4.shared.b16 {%0,%1,%2,%3}, [%4];" \
        : "=r"((r)[0]), "=r"((r)[1]), "=r"((r)[2]), "=r"((r)[3]) : "r"(addr))
#define MMA_BF16(c, a, b) \
    asm volatile("mma.sync.aligned.m16n8k16.row.col.f32.bf16.bf16.f32 " \
        "{%0,%1,%2,%3}, {%4,%5,%6,%7}, {%8,%9}, {%0,%1,%2,%3};" \
        : "+f"((c)[0]), "+f"((c)[1]), "+f"((c)[2]), "+f"((c)[3]) \
        : "r"((a)[0]), "r"((a)[1]), "r"((a)[2]), "r"((a)[3]), "r"((b)[0]), "r"((b)[1]))
#define CP_ASYNC16(dst, src) \
    asm volatile("cp.async.cg.shared.global [%0], [%1], 16;" :: "r"(dst), "l"(src))
#define CP_COMMIT() asm volatile("cp.async.commit_group;" ::: "memory")
#define CP_WAIT0()  asm volatile("cp.async.wait_group 0;" ::: "memory")

__device__ __forceinline__ uint32_t pack2bf(float x, float y) {
    __nv_bfloat16 bx = __float2bfloat16_rn(x), by = __float2bfloat16_rn(y);
    return ((uint32_t)__bfloat16_as_ushort(by) << 16) | (uint32_t)__bfloat16_as_ushort(bx);
}
__device__ __forceinline__ uint32_t sw64(uint32_t o) { return o ^ ((o >> 3) & 0x30); }

// ============================================================
// K1: per-molecule prep (unchanged)
// ============================================================
__global__ void mol_prep(const float* __restrict__ E, const float* __restrict__ Wq,
                         const float* __restrict__ bq, const float* __restrict__ Wk,
                         const float* __restrict__ Wv, int B) {
    __shared__ float k_s[16][F_DIM];
    __shared__ float e_s[16][2], en_s[16][2];
    __shared__ float red[8];
    int tid = threadIdx.x;
    int b0  = blockIdx.x * 16;

    if (tid < 16) {
        int mol = b0 + tid;
        float Ev = (mol < B) ? E[mol] : 0.f;
        float e0 = fmaxf(Ev, 0.f), e1 = fmaxf(-Ev, 0.f);
        e_s[tid][0]  = e0;             e_s[tid][1]  = e1;
        en_s[tid][0] = fminf(e0, 1.f); en_s[tid][1] = fminf(e1, 1.f);
    }
    __syncthreads();

    float wk0 = Wk[tid * 2], wk1 = Wk[tid * 2 + 1];
    float wv0 = Wv[tid * 2], wv1 = Wv[tid * 2 + 1];
    #pragma unroll
    for (int b = 0; b < 16; b++) {
        float kv = en_s[b][0] * wk0 + en_s[b][1] * wk1;
        k_s[b][tid] = kv;
        int mol = b0 + b;
        if (mol < B) g_vmol[mol * F_DIM + tid] = e_s[b][0] * wv0 + e_s[b][1] * wv1;
    }
    __syncthreads();

    float acc[16];
    #pragma unroll
    for (int b = 0; b < 16; b++) acc[b] = 0.f;
    for (int f = 0; f < F_DIM; f++) {
        float w = Wq[f * F_DIM + tid];
        #pragma unroll
        for (int b = 0; b < 16; b++) acc[b] += k_s[b][f] * w;
    }
    #pragma unroll
    for (int b = 0; b < 16; b++) {
        int mol = b0 + b;
        if (mol < B) g_kq[mol * F_DIM + tid] = acc[b];
    }

    float bqv = bq[tid];
    int lane = tid & 31, wid = tid >> 5;
    for (int b = 0; b < 16; b++) {
        float v = k_s[b][tid] * bqv;
        #pragma unroll
        for (int o = 16; o > 0; o >>= 1) v += __shfl_down_sync(0xffffffffu, v, o);
        if (lane == 0) red[wid] = v;
        __syncthreads();
        if (tid == 0) {
            float s = 0.f;
            #pragma unroll
            for (int w = 0; w < 8; w++) s += red[w];
            int mol = b0 + b;
            if (mol < B) g_kb[mol] = s;
        }
        __syncthreads();
    }
}

// ============================================================
// K2: per-atom score (unchanged)
// ============================================================
__global__ void atom_score(const float* __restrict__ x, const int* __restrict__ idx, int N) {
    __shared__ float wsum[8];
    int tid = threadIdx.x, lane = tid & 31, wid = tid >> 5;
    int n = blockIdx.x * 8 + wid;
    float a = 0.f;
    if (n < N) {
        int m = idx[n];
        const float* xr = x    + (size_t)n * F_DIM;
        const float* kq = g_kq + (size_t)m * F_DIM;
        float s = 0.f;
        #pragma unroll
        for (int j = 0; j < 8; j++) { int c = lane + j * 32; s += xr[c] * kq[c]; }
        #pragma unroll
        for (int o = 16; o > 0; o >>= 1) s += __shfl_down_sync(0xffffffffu, s, o);
        if (lane == 0) {
            float d = (s + g_kb[m]) * 0.0625f;
            a = fmaxf(d, 0.f) + log1pf(expf(-fabsf(d)));
            g_a[n] = a;
        }
    }
    if (lane == 0) wsum[wid] = a;
    __syncthreads();
    if (tid == 0) {
        float t = 0.f;
        #pragma unroll
        for (int w = 0; w < 8; w++) t += wsum[w];
        g_part[blockIdx.x] = t;
    }
}

// ============================================================
// K3: fused normalization + weight split (one launch)
// block 0: reduce partials -> g_inv; blocks 1..: bf16 hi/lo split
// ============================================================
__global__ void prep_misc(const float* __restrict__ W1, const float* __restrict__ W2,
                          const float* __restrict__ Wout, int R, int nparts) {
    int tid = threadIdx.x;
    if (blockIdx.x == 0) {
        __shared__ float red[256];
        float s = 0.f;
        for (int i = tid; i < nparts; i += 256) s += g_part[i];
        red[tid] = s;
        __syncthreads();
        for (int o = 128; o > 0; o >>= 1) {
            if (tid < o) red[tid] += red[tid + o];
            __syncthreads();
        }
        if (tid == 0) g_inv[0] = 1.f / (red[0] + 1e-8f);
        return;
    }
    int i = (blockIdx.x - 1) * 256 + tid;
    int total = (2 * R + 1) * F_DIM * F_DIM;
    if (i >= total) return;
    int slot = i >> 16, j = i & 65535;
    const float* src = (slot == 2 * R) ? (Wout + j)
                     : (((slot & 1) ? W2 : W1) + (size_t)(slot >> 1) * 65536 + j);
    float w = *src;
    __nv_bfloat16 hi = __float2bfloat16_rn(w);
    __nv_bfloat16 lo = __float2bfloat16_rn(w - __bfloat162float(hi));
    g_Whi[i] = hi;
    g_Wlo[i] = lo;
}

// ============================================================
// K4: fused kernel.
// mode 0 (residual block): y1 = swish1(h)@W1^T (phase 1, y1 -> smem),
//                          y2 = swish2(y1)@W2^T (phase 2), g_H = h + y2.
//   Acode 3: h = virtual gather (a*inv*vmol);  Acode 0: h = g_H.
// mode 1 (final): out = swish1(g_H)@W[slot1]^T.
// CTA: 128 rows x 256 cols, 512 threads (16 warps: 2m x 8n, warp 64x32).
// ============================================================
#define BK 64
#define NCHUNK (F_DIM / BK)
#define PITCH 144
#define A_T 18432                // 128*144 (phase1 A chunk / y1 chunk)
#define B_T 36864                // 256*144 (phase1 B chunk)
#define B2_T 16384               // 256*64 sw64 (phase2 B chunk)
#define SM_AL1 0
#define SM_BE1 1024
#define SM_AL2 2048
#define SM_BE2 3072
#define SM_RSC 4096
#define SM_RM  4608
#define RG1    5120              // 73728: phase1 A (db*2+h)*A_T; phase2 B (db*2+h)*B2_T
#define RG2    (5120 + 73728)    // 147456: phase1 B (db*2+h)*B_T; y1 (cb*2+h)*A_T
#define SMT    (RG2 + 147456)    // 226304 bytes

__global__ void __launch_bounds__(512, 1) fused_rb(
    int Acode, int slot1, int slot2,
    const float* __restrict__ al1, const float* __restrict__ be1,
    const float* __restrict__ al2, const float* __restrict__ be2,
    float* outp, const int* __restrict__ idx, int Nrows, int mode) {
    extern __shared__ char smem[];
    const uint32_t sb = smem_u32(smem);
    const int tid  = threadIdx.x;
    const int lane = tid & 31, wrp = tid >> 5;
    const int warpM = wrp >> 3, warpN = wrp & 7;
    const int m0 = blockIdx.x * 128;

    float* sAl1 = (float*)(smem + SM_AL1);
    float* sBe1 = (float*)(smem + SM_BE1);
    float* sAl2 = (float*)(smem + SM_AL2);
    float* sBe2 = (float*)(smem + SM_BE2);
    float* sRsc = (float*)(smem + SM_RSC);
    int*   sRm  = (int*)  (smem + SM_RM);

    if (tid < 256) {
        sAl1[tid] = al1[tid]; sBe1[tid] = be1[tid];
        sAl2[tid] = al2[tid]; sBe2[tid] = be2[tid];
    }
    if (tid < 128) {
        int grow = m0 + tid;
        if (grow < Nrows) { sRsc[tid] = g_a[grow] * g_inv[0]; sRm[tid] = idx[grow]; }
        else              { sRsc[tid] = 0.f; sRm[tid] = 0; }
    }
    __syncthreads();

    const float* Asrc = g_H;   // used when Acode==0 or mode==1
    const __nv_bfloat16* B1b[2] = { g_Whi + (size_t)slot1 * 65536, g_Wlo + (size_t)slot1 * 65536 };
    const __nv_bfloat16* B2b[2] = { g_Whi + (size_t)slot2 * 65536, g_Wlo + (size_t)slot2 * 65536 };

    float acc[4][4][4];
    #pragma unroll
    for (int i = 0; i < 4; i++)
        #pragma unroll
        for (int j = 0; j < 4; j++)
            #pragma unroll
            for (int l = 0; l < 4; l++) acc[i][j][l] = 0.f;

    // ================= phase 1 =================
    auto cpB = [&](int c, int db) {
        const int k0 = c * BK;
        #pragma unroll
        for (int i = 0; i < 8; i++) {
            int t = tid + i * 512;
            int sp = t >> 11, w = t & 2047;
            int row = w >> 3, c16 = w & 7;
            const __nv_bfloat16* src = B1b[sp] + (size_t)row * F_DIM + k0 + c16 * 8;
            uint32_t dst = sb + RG2 + (uint32_t)(db * 2 + sp) * B_T + (uint32_t)row * PITCH + c16 * 16;
            CP_ASYNC16(dst, src);
        }
        CP_COMMIT();
    };
    float4 pa[4];
    auto prefetchA = [&](int c) {
        const int k0 = c * BK;
        #pragma unroll
        for (int i = 0; i < 4; i++) {
            int q = tid + i * 512;
            int r = q >> 4, c4 = q & 15;
            int grow = m0 + r;
            float4 v = make_float4(0.f, 0.f, 0.f, 0.f);
            if (grow < Nrows) {
                if (Acode == 3)
                    v = ((const float4*)(g_vmol + (size_t)sRm[r] * F_DIM + k0))[c4];
                else
                    v = ((const float4*)(Asrc + (size_t)grow * F_DIM + k0))[c4];
            }
            pa[i] = v;
        }
    };
    auto stsA = [&](int c, int db) {
        const int k0 = c * BK;
        char* ahd = smem + RG1 + (size_t)(db * 2 + 0) * A_T;
        char* ald = smem + RG1 + (size_t)(db * 2 + 1) * A_T;
        #pragma unroll
        for (int i = 0; i < 4; i++) {
            int q = tid + i * 512;
            int r = q >> 4, c4 = q & 15;
            float vals[4] = {pa[i].x, pa[i].y, pa[i].z, pa[i].w};
            float sc = (Acode == 3) ? sRsc[r] : 1.f;
            float hi[4], lo[4];
            #pragma unroll
            for (int j = 0; j < 4; j++) {
                int col = k0 + c4 * 4 + j;
                float xv = sc * vals[j];
                float s  = sBe1[col] * xv;
                float sw = sAl1[col] * s * (1.f / (1.f + __expf(-s)));
                __nv_bfloat16 bh = __float2bfloat16_rn(sw);
                hi[j] = __bfloat162float(bh);
                lo[j] = sw - hi[j];
            }
            uint32_t o = (uint32_t)(r * PITCH + c4 * 8);
            *(uint2*)(ahd + o) = make_uint2(pack2bf(hi[0], hi[1]), pack2bf(hi[2], hi[3]));
            *(uint2*)(ald + o) = make_uint2(pack2bf(lo[0], lo[1]), pack2bf(lo[2], lo[3]));
        }
    };

    cpB(0, 0);
    prefetchA(0);
    stsA(0, 0);
    CP_WAIT0();
    __syncthreads();

    const int rowA = warpM * 64 + (lane & 15);
    const int rowB = warpN * 32 + (lane & 7) + ((lane >> 4) << 3);
    const uint32_t aAddr0 = sb + RG1 + (uint32_t)rowA * PITCH + ((lane >> 4) * 16);
    const uint32_t bAddr0 = sb + RG2 + (uint32_t)rowB * PITCH + (((lane >> 3) & 1) * 16);

    for (int c = 0; c < NCHUNK; c++) {
        const int db = c & 1;
        if (c + 1 < NCHUNK) { cpB(c + 1, db ^ 1); prefetchA(c + 1); }
        const uint32_t aB = aAddr0 + (uint32_t)(db * 2) * A_T;
        const uint32_t bB = bAddr0 + (uint32_t)(db * 2) * B_T;
        #pragma unroll
        for (int s = 0; s < 4; s++) {
            uint32_t bh[4][2], bl[4][2];
            #pragma unroll
            for (int ntp = 0; ntp < 2; ntp++) {
                uint32_t t4[4];
                uint32_t ab = bB + ntp * (16 * PITCH) + s * 32;
                LDSM_X4(t4, ab);
                bh[2*ntp][0] = t4[0]; bh[2*ntp][1] = t4[1];
                bh[2*ntp+1][0] = t4[2]; bh[2*ntp+1][1] = t4[3];
                LDSM_X4(t4, ab + B_T);
                bl[2*ntp][0] = t4[0]; bl[2*ntp][1] = t4[1];
                bl[2*ntp+1][0] = t4[2]; bl[2*ntp+1][1] = t4[3];
            }
            #pragma unroll
            for (int mt = 0; mt < 4; mt++) {
                uint32_t aa = aB + mt * (16 * PITCH) + s * 32;
                uint32_t ah[4], alr[4];
                LDSM_X4(ah, aa);
                LDSM_X4(alr, aa + A_T);
                #pragma unroll
                for (int nt = 0; nt < 4; nt++) {
                    MMA_BF16(acc[mt][nt], ah,  bh[nt]);
                    MMA_BF16(acc[mt][nt], ah,  bl[nt]);
                    MMA_BF16(acc[mt][nt], alr, bh[nt]);
                }
            }
        }
        if (c + 1 < NCHUNK) { stsA(c + 1, db ^ 1); CP_WAIT0(); }
        __syncthreads();
    }

    const int rfrag = warpM * 64 + (lane >> 2);
    const int cfrag = warpN * 32 + (lane & 3) * 2;

    if (mode == 1) {
        // final GEMM: write out
        #pragma unroll
        for (int mt = 0; mt < 4; mt++)
            #pragma unroll
            for (int rh = 0; rh < 2; rh++) {
                int grow = m0 + rfrag + mt * 16 + rh * 8;
                if (grow >= Nrows) continue;
                float* cp = outp + (size_t)grow * F_DIM + cfrag;
                #pragma unroll
                for (int nt = 0; nt < 4; nt++)
                    *(float2*)(cp + nt * 8) = make_float2(acc[mt][nt][rh*2], acc[mt][nt][rh*2+1]);
            }
        return;
    }

    // ================= phase 2 =================
    auto cpB2 = [&](int c, int db) {
        const int kc = c * 32;
        #pragma unroll
        for (int i = 0; i < 4; i++) {
            int t = tid + i * 512;
            int sp = t >> 10, w = t & 1023;
            int row = w >> 2, c16 = w & 3;
            const __nv_bfloat16* src = B2b[sp] + (size_t)row * F_DIM + kc + c16 * 8;
            uint32_t dst = sb + RG1 + (uint32_t)(db * 2 + sp) * B2_T + sw64((uint32_t)(row * 64 + c16 * 16));
            CP_ASYNC16(dst, src);
        }
        CP_COMMIT();
    };

    // start loading W2 chunk 0 while converting y1 (writes RG1 which phase1 A is done with)
    cpB2(0, 0);

    // convert acc -> y1 smem (swish2 + bf16 split), into RG2 (phase1 B region, done)
    #pragma unroll
    for (int mt = 0; mt < 4; mt++)
        #pragma unroll
        for (int rh = 0; rh < 2; rh++) {
            int row = rfrag + mt * 16 + rh * 8;
            #pragma unroll
            for (int nt = 0; nt < 4; nt++) {
                int col = cfrag + nt * 8;
                float v0 = acc[mt][nt][rh*2], v1 = acc[mt][nt][rh*2+1];
                float s0 = sBe2[col] * v0, s1 = sBe2[col+1] * v1;
                float w0 = sAl2[col]   * s0 * (1.f / (1.f + __expf(-s0)));
                float w1 = sAl2[col+1] * s1 * (1.f / (1.f + __expf(-s1)));
                __nv_bfloat16 b0 = __float2bfloat16_rn(w0), b1 = __float2bfloat16_rn(w1);
                float h0 = __bfloat162float(b0), h1 = __bfloat162float(b1);
                int cb = col >> 6;
                uint32_t o = (uint32_t)(row * PITCH + (col & 63) * 2);
                char* base = smem + RG2 + (size_t)(cb * 2) * A_T;
                *(uint32_t*)(base + o)       = pack2bf(h0, h1);
                *(uint32_t*)(base + A_T + o) = pack2bf(w0 - h0, w1 - h1);
            }
        }
    #pragma unroll
    for (int i = 0; i < 4; i++)
        #pragma unroll
        for (int j = 0; j < 4; j++)
            #pragma unroll
            for (int l = 0; l < 4; l++) acc[i][j][l] = 0.f;

    CP_WAIT0();
    __syncthreads();

    for (int c = 0; c < 8; c++) {
        const int db = c & 1;
        if (c + 1 < 8) cpB2(c + 1, db ^ 1);
        const int cb  = c >> 1;
        const int kof = (c & 1) * 64;           // byte offset of this 32-k half in 128B row
        const uint32_t aB2 = sb + RG2 + (uint32_t)(cb * 2) * A_T + (uint32_t)rowA * PITCH + kof + ((lane >> 4) * 16);
        #pragma unroll
        for (int s = 0; s < 2; s++) {
            uint32_t bh[4][2], bl[4][2];
            #pragma unroll
            for (int ntp = 0; ntp < 2; ntp++) {
                uint32_t t4[4];
                uint32_t boff = sw64((uint32_t)((rowB + ntp * 16) * 64 + s * 32 + ((lane >> 3) & 1) * 16));
                uint32_t ab = sb + RG1 + (uint32_t)(db * 2) * B2_T + boff;
                LDSM_X4(t4, ab);
                bh[2*ntp][0] = t4[0]; bh[2*ntp][1] = t4[1];
                bh[2*ntp+1][0] = t4[2]; bh[2*ntp+1][1] = t4[3];
                LDSM_X4(t4, ab + B2_T);
                bl[2*ntp][0] = t4[0]; bl[2*ntp][1] = t4[1];
                bl[2*ntp+1][0] = t4[2]; bl[2*ntp+1][1] = t4[3];
            }
            #pragma unroll
            for (int mt = 0; mt < 4; mt++) {
                uint32_t aa = aB2 + mt * (16 * PITCH) + s * 32;
                uint32_t ah[4], alr[4];
                LDSM_X4(ah, aa);
                LDSM_X4(alr, aa + A_T);
                #pragma unroll
                for (int nt = 0; nt < 4; nt++) {
                    MMA_BF16(acc[mt][nt], ah,  bh[nt]);
                    MMA_BF16(acc[mt][nt], ah,  bl[nt]);
                    MMA_BF16(acc[mt][nt], alr, bh[nt]);
                }
            }
        }
        CP_WAIT0();
        __syncthreads();
    }

    // epilogue: g_H = h + y2
    #pragma unroll
    for (int mt = 0; mt < 4; mt++)
        #pragma unroll
        for (int rh = 0; rh < 2; rh++) {
            int lr = rfrag + mt * 16 + rh * 8;
            int grow = m0 + lr;
            if (grow >= Nrows) continue;
            float* hp = g_H + (size_t)grow * F_DIM + cfrag;
            #pragma unroll
            for (int nt = 0; nt < 4; nt++) {
                float v0 = acc[mt][nt][rh*2], v1 = acc[mt][nt][rh*2+1];
                if (Acode == 3) {
                    const float* vp = g_vmol + (size_t)sRm[lr] * F_DIM + cfrag + nt * 8;
                    float sc = sRsc[lr];
                    v0 += sc * vp[0]; v1 += sc * vp[1];
                } else {
                    float2 o = *(float2*)(hp + nt * 8);
                    v0 += o.x; v1 += o.y;
                }
                *(float2*)(hp + nt * 8) = make_float2(v0, v1);
            }
        }
}

// ============================================================
extern "C" void kernel_launch(void* const* d_in, const int* in_sizes, int n_in,
                              void* d_out, int out_size) {
    const float* x    = (const float*)d_in[0];
    const float* E    = (const float*)d_in[1];
    const int*   asi  = (const int*)  d_in[2];
    const float* Wq   = (const float*)d_in[3];
    const float* bq   = (const float*)d_in[4];
    const float* Wk   = (const float*)d_in[5];
    const float* Wv   = (const float*)d_in[6];
    const float* W1   = (const float*)d_in[7];
    const float* W2   = (const float*)d_in[8];
    const float* a1   = (const float*)d_in[9];
    const float* b1   = (const float*)d_in[10];
    const float* a2   = (const float*)d_in[11];
    const float* b2   = (const float*)d_in[12];
    const float* oa   = (const float*)d_in[13];
    const float* ob   = (const float*)d_in[14];
    const float* Wout = (const float*)d_in[15];

    int B = in_sizes[1];
    int N = in_sizes[2];
    int R = in_sizes[7] / (F_DIM * F_DIM);
    float* out = (float*)d_out;

    cudaFuncSetAttribute(fused_rb, cudaFuncAttributeMaxDynamicSharedMemorySize, SMT);

    mol_prep<<<(B + 15) / 16, 256>>>(E, Wq, bq, Wk, Wv, B);          // 0

    int gS = (N + 7) / 8;
    atom_score<<<gS, 256>>>(x, asi, N);                               // 1

    int wblocks = ((2 * R + 1) * F_DIM * F_DIM + 255) / 256;
    prep_misc<<<1 + wblocks, 256>>>(W1, W2, Wout, R, gS);             // 2

    int grid = (N + 127) / 128;
    for (int i = 0; i < R; i++) {                                     // 3, 4
        fused_rb<<<grid, 512, SMT>>>((i == 0) ? 3 : 0, 2 * i, 2 * i + 1,
                                     a1 + i * F_DIM, b1 + i * F_DIM,
                                     a2 + i * F_DIM, b2 + i * F_DIM,
                                     out, asi, N, 0);
    }
    fused_rb<<<grid, 512, SMT>>>(0, 2 * R, 0, oa, ob, oa, ob,         // 5
                                 out, asi, N, 1);
}

// round 6
// speedup vs baseline: 1.2377x; 1.2377x over previous
#include <cuda_runtime.h>
#include <cuda_bf16.h>
#include <math.h>
#include <stdint.h>

#define F_DIM 256
#define N_MAX 200000
#define B_MAX 4000

// ---- scratch (device globals: allocation-free) ----
__device__ float g_kq[B_MAX * F_DIM];
__device__ float g_kb[B_MAX];
__device__ float g_vmol[B_MAX * F_DIM];
__device__ float g_a[N_MAX];
__device__ float g_part[(N_MAX + 7) / 8];
__device__ float g_inv[1];
__device__ float g_H[(size_t)N_MAX * F_DIM];
__device__ float g_Y[(size_t)N_MAX * F_DIM];
__device__ __nv_bfloat16 g_Whi[5 * F_DIM * F_DIM];
__device__ __nv_bfloat16 g_Wlo[5 * F_DIM * F_DIM];

// ============================================================
// helpers
// ============================================================
__device__ __forceinline__ uint32_t smem_u32(const void* p) {
    uint32_t a;
    asm("{ .reg .u64 t; cvta.to.shared.u64 t, %1; cvt.u32.u64 %0, t; }" : "=r"(a) : "l"(p));
    return a;
}
#define LDSM_X4(r, addr) \
    asm volatile("ldmatrix.sync.aligned.m8n8.x4.shared.b16 {%0,%1,%2,%3}, [%4];" \
        : "=r"((r)[0]), "=r"((r)[1]), "=r"((r)[2]), "=r"((r)[3]) : "r"(addr))
#define MMA_BF16(c, a, b) \
    asm volatile("mma.sync.aligned.m16n8k16.row.col.f32.bf16.bf16.f32 " \
        "{%0,%1,%2,%3}, {%4,%5,%6,%7}, {%8,%9}, {%0,%1,%2,%3};" \
        : "+f"((c)[0]), "+f"((c)[1]), "+f"((c)[2]), "+f"((c)[3]) \
        : "r"((a)[0]), "r"((a)[1]), "r"((a)[2]), "r"((a)[3]), "r"((b)[0]), "r"((b)[1]))
#define CP_ASYNC16(dst, src) \
    asm volatile("cp.async.cg.shared.global [%0], [%1], 16;" :: "r"(dst), "l"(src))
#define CP_COMMIT() asm volatile("cp.async.commit_group;" ::: "memory")
#define CP_WAIT0()  asm volatile("cp.async.wait_group 0;" ::: "memory")

__device__ __forceinline__ uint32_t pack2bf(float x, float y) {
    __nv_bfloat16 bx = __float2bfloat16_rn(x), by = __float2bfloat16_rn(y);
    return ((uint32_t)__bfloat16_as_ushort(by) << 16) | (uint32_t)__bfloat16_as_ushort(bx);
}

// ============================================================
// K1: per-molecule prep (unchanged)
// ============================================================
__global__ void mol_prep(const float* __restrict__ E, const float* __restrict__ Wq,
                         const float* __restrict__ bq, const float* __restrict__ Wk,
                         const float* __restrict__ Wv, int B) {
    __shared__ float k_s[16][F_DIM];
    __shared__ float e_s[16][2], en_s[16][2];
    __shared__ float red[8];
    int tid = threadIdx.x;
    int b0  = blockIdx.x * 16;

    if (tid < 16) {
        int mol = b0 + tid;
        float Ev = (mol < B) ? E[mol] : 0.f;
        float e0 = fmaxf(Ev, 0.f), e1 = fmaxf(-Ev, 0.f);
        e_s[tid][0]  = e0;             e_s[tid][1]  = e1;
        en_s[tid][0] = fminf(e0, 1.f); en_s[tid][1] = fminf(e1, 1.f);
    }
    __syncthreads();

    float wk0 = Wk[tid * 2], wk1 = Wk[tid * 2 + 1];
    float wv0 = Wv[tid * 2], wv1 = Wv[tid * 2 + 1];
    #pragma unroll
    for (int b = 0; b < 16; b++) {
        float kv = en_s[b][0] * wk0 + en_s[b][1] * wk1;
        k_s[b][tid] = kv;
        int mol = b0 + b;
        if (mol < B) g_vmol[mol * F_DIM + tid] = e_s[b][0] * wv0 + e_s[b][1] * wv1;
    }
    __syncthreads();

    float acc[16];
    #pragma unroll
    for (int b = 0; b < 16; b++) acc[b] = 0.f;
    for (int f = 0; f < F_DIM; f++) {
        float w = Wq[f * F_DIM + tid];
        #pragma unroll
        for (int b = 0; b < 16; b++) acc[b] += k_s[b][f] * w;
    }
    #pragma unroll
    for (int b = 0; b < 16; b++) {
        int mol = b0 + b;
        if (mol < B) g_kq[mol * F_DIM + tid] = acc[b];
    }

    float bqv = bq[tid];
    int lane = tid & 31, wid = tid >> 5;
    for (int b = 0; b < 16; b++) {
        float v = k_s[b][tid] * bqv;
        #pragma unroll
        for (int o = 16; o > 0; o >>= 1) v += __shfl_down_sync(0xffffffffu, v, o);
        if (lane == 0) red[wid] = v;
        __syncthreads();
        if (tid == 0) {
            float s = 0.f;
            #pragma unroll
            for (int w = 0; w < 8; w++) s += red[w];
            int mol = b0 + b;
            if (mol < B) g_kb[mol] = s;
        }
        __syncthreads();
    }
}

// ============================================================
// K2: per-atom score (unchanged)
// ============================================================
__global__ void atom_score(const float* __restrict__ x, const int* __restrict__ idx, int N) {
    __shared__ float wsum[8];
    int tid = threadIdx.x, lane = tid & 31, wid = tid >> 5;
    int n = blockIdx.x * 8 + wid;
    float a = 0.f;
    if (n < N) {
        int m = idx[n];
        const float* xr = x    + (size_t)n * F_DIM;
        const float* kq = g_kq + (size_t)m * F_DIM;
        float s = 0.f;
        #pragma unroll
        for (int j = 0; j < 8; j++) { int c = lane + j * 32; s += xr[c] * kq[c]; }
        #pragma unroll
        for (int o = 16; o > 0; o >>= 1) s += __shfl_down_sync(0xffffffffu, s, o);
        if (lane == 0) {
            float d = (s + g_kb[m]) * 0.0625f;
            a = fmaxf(d, 0.f) + log1pf(expf(-fabsf(d)));
            g_a[n] = a;
        }
    }
    if (lane == 0) wsum[wid] = a;
    __syncthreads();
    if (tid == 0) {
        float t = 0.f;
        #pragma unroll
        for (int w = 0; w < 8; w++) t += wsum[w];
        g_part[blockIdx.x] = t;
    }
}

// ============================================================
// K3: fused normalization + weight split (one launch)
// ============================================================
__global__ void prep_misc(const float* __restrict__ W1, const float* __restrict__ W2,
                          const float* __restrict__ Wout, int R, int nparts) {
    int tid = threadIdx.x;
    if (blockIdx.x == 0) {
        __shared__ float red[256];
        float s = 0.f;
        for (int i = tid; i < nparts; i += 256) s += g_part[i];
        red[tid] = s;
        __syncthreads();
        for (int o = 128; o > 0; o >>= 1) {
            if (tid < o) red[tid] += red[tid + o];
            __syncthreads();
        }
        if (tid == 0) g_inv[0] = 1.f / (red[0] + 1e-8f);
        return;
    }
    int i = (blockIdx.x - 1) * 256 + tid;
    int total = (2 * R + 1) * F_DIM * F_DIM;
    if (i >= total) return;
    int slot = i >> 16, j = i & 65535;
    const float* src = (slot == 2 * R) ? (Wout + j)
                     : (((slot & 1) ? W2 : W1) + (size_t)(slot >> 1) * 65536 + j);
    float w = *src;
    __nv_bfloat16 hi = __float2bfloat16_rn(w);
    __nv_bfloat16 lo = __float2bfloat16_rn(w - __bfloat162float(hi));
    g_Whi[i] = hi;
    g_Wlo[i] = lo;
}

// ============================================================
// K4: warp-mma bf16 split-3 GEMM.
// CTA: 128 rows x 128 cols, 256 threads (8 warps: 2m x 4n, warp 64x32).
// BK=32, cp.async B, double-buffered; 2 CTAs/SM for sync overlap.
// A codes: 0=g_H, 1=g_Y, 3=virtual h. C codes: 0=g_H, 1=g_Y, 2=out.
// accmode: 0=store, 1=C+=acc, 2=C=gather_h+acc
// ============================================================
#define BK 32
#define NCHUNK (F_DIM / BK)
#define PITCH 80                   // 64B data + 16B pad (conflict-free, proven R3)
#define A_TILE (128 * PITCH)       // 10240
#define B_TILE (128 * PITCH)       // 10240
#define SM_AL   0
#define SM_BE   1024
#define SM_RSC  2048
#define SM_RM   2560
#define SM_A    3072                       // [db(2)][hilo(2)] x A_TILE = 40960
#define SM_B    (3072 + 4 * A_TILE)        // [db(2)][hilo(2)] x B_TILE = 40960
#define SM_TOTAL (SM_B + 4 * B_TILE)       // 84992 bytes

__global__ void __launch_bounds__(256, 2) gemm_tc(
    int Acode, int slot, const float* __restrict__ al, const float* __restrict__ be,
    int Ccode, int accmode, float* outp, const int* __restrict__ idx, int Nrows) {
    extern __shared__ char smem[];
    const uint32_t sb = smem_u32(smem);
    const int tid  = threadIdx.x;
    const int lane = tid & 31, wrp = tid >> 5;
    const int warpM = wrp >> 2, warpN = wrp & 3;   // 2 x 4
    const int m0 = blockIdx.x * 128;
    const int n0 = blockIdx.y * 128;

    float* sAl  = (float*)(smem + SM_AL);
    float* sBe  = (float*)(smem + SM_BE);
    float* sRsc = (float*)(smem + SM_RSC);
    int*   sRm  = (int*)  (smem + SM_RM);

    if (tid < 256) { sAl[tid] = al[tid]; sBe[tid] = be[tid]; }
    {
        int r = tid >> 1;
        if ((tid & 1) == 0) {
            int grow = m0 + r;
            if (grow < Nrows) { sRsc[r] = g_a[grow] * g_inv[0]; sRm[r] = idx[grow]; }
            else              { sRsc[r] = 0.f; sRm[r] = 0; }
        }
    }
    __syncthreads();

    const float* Asrc = (Acode == 0) ? g_H : (Acode == 1) ? g_Y : (const float*)0;
    const __nv_bfloat16* Bbase[2] = { g_Whi + (size_t)slot * 65536 + (size_t)n0 * F_DIM,
                                      g_Wlo + (size_t)slot * 65536 + (size_t)n0 * F_DIM };

    float acc[4][4][4];
    #pragma unroll
    for (int i = 0; i < 4; i++)
        #pragma unroll
        for (int j = 0; j < 4; j++)
            #pragma unroll
            for (int l = 0; l < 4; l++) acc[i][j][l] = 0.f;

    // ---- B: cp.async gmem->smem, 4 x 16B per thread per chunk ----
    auto cpB = [&](int c, int db) {
        const int k0 = c * BK;
        #pragma unroll
        for (int i = 0; i < 4; i++) {
            int t   = tid + i * 256;        // 0..1023
            int sp  = t >> 9;               // 0=hi, 1=lo
            int w   = t & 511;
            int row = w >> 2, c16 = w & 3;
            const __nv_bfloat16* src = Bbase[sp] + (size_t)row * F_DIM + k0 + c16 * 8;
            uint32_t dst = sb + SM_B + (uint32_t)(db * 2 + sp) * B_TILE
                         + (uint32_t)row * PITCH + c16 * 16;
            CP_ASYNC16(dst, src);
        }
        CP_COMMIT();
    };

    // ---- A: LDG prefetch (4 float4 / thread) ----
    float4 pa[4];
    auto prefetchA = [&](int c) {
        const int k0 = c * BK;
        #pragma unroll
        for (int i = 0; i < 4; i++) {
            int q = tid + i * 256;          // 0..1023
            int r = q >> 3, c4 = q & 7;     // 8 float4 per row
            int grow = m0 + r;
            float4 v = make_float4(0.f, 0.f, 0.f, 0.f);
            if (grow < Nrows) {
                if (Acode == 3)
                    v = ((const float4*)(g_vmol + (size_t)sRm[r] * F_DIM + k0))[c4];
                else
                    v = ((const float4*)(Asrc + (size_t)grow * F_DIM + k0))[c4];
            }
            pa[i] = v;
        }
    };
    // ---- A: swish + split + store to smem ----
    auto stsA = [&](int c, int db) {
        const int k0 = c * BK;
        char* ahd = smem + SM_A + (size_t)(db * 2 + 0) * A_TILE;
        char* ald = smem + SM_A + (size_t)(db * 2 + 1) * A_TILE;
        #pragma unroll
        for (int i = 0; i < 4; i++) {
            int q = tid + i * 256;
            int r = q >> 3, c4 = q & 7;
            float vals[4] = {pa[i].x, pa[i].y, pa[i].z, pa[i].w};
            float sc = (Acode == 3) ? sRsc[r] : 1.f;
            float hi[4], lo[4];
            #pragma unroll
            for (int j = 0; j < 4; j++) {
                int col = k0 + c4 * 4 + j;
                float xv = sc * vals[j];
                float s  = sBe[col] * xv;
                float sw = sAl[col] * s * (1.f / (1.f + __expf(-s)));
                __nv_bfloat16 bh = __float2bfloat16_rn(sw);
                hi[j] = __bfloat162float(bh);
                lo[j] = sw - hi[j];
            }
            uint32_t o = (uint32_t)(r * PITCH + c4 * 8);
            *(uint2*)(ahd + o) = make_uint2(pack2bf(hi[0], hi[1]), pack2bf(hi[2], hi[3]));
            *(uint2*)(ald + o) = make_uint2(pack2bf(lo[0], lo[1]), pack2bf(lo[2], lo[3]));
        }
    };

    // prologue: chunk 0
    cpB(0, 0);
    prefetchA(0);
    stsA(0, 0);
    CP_WAIT0();
    __syncthreads();

    const uint32_t aAddr0 = sb + SM_A + (uint32_t)(warpM * 64 + (lane & 15)) * PITCH
                          + ((lane >> 4) * 16);
    const uint32_t bAddr0 = sb + SM_B
                          + (uint32_t)(warpN * 32 + (lane & 7) + ((lane >> 4) << 3)) * PITCH
                          + (((lane >> 3) & 1) * 16);

    for (int c = 0; c < NCHUNK; c++) {
        const int db = c & 1;
        if (c + 1 < NCHUNK) { cpB(c + 1, db ^ 1); prefetchA(c + 1); }

        const uint32_t aB = aAddr0 + (uint32_t)(db * 2) * A_TILE;
        const uint32_t bB = bAddr0 + (uint32_t)(db * 2) * B_TILE;
        #pragma unroll
        for (int s = 0; s < 2; s++) {
            uint32_t bh[4][2], bl[4][2];
            #pragma unroll
            for (int ntp = 0; ntp < 2; ntp++) {
                uint32_t t4[4];
                uint32_t ab = bB + ntp * (16 * PITCH) + s * 32;
                LDSM_X4(t4, ab);
                bh[2*ntp][0] = t4[0]; bh[2*ntp][1] = t4[1];
                bh[2*ntp+1][0] = t4[2]; bh[2*ntp+1][1] = t4[3];
                LDSM_X4(t4, ab + B_TILE);
                bl[2*ntp][0] = t4[0]; bl[2*ntp][1] = t4[1];
                bl[2*ntp+1][0] = t4[2]; bl[2*ntp+1][1] = t4[3];
            }
            #pragma unroll
            for (int mt = 0; mt < 4; mt++) {
                uint32_t aa = aB + mt * (16 * PITCH) + s * 32;
                uint32_t ah[4], alr[4];
                LDSM_X4(ah, aa);
                LDSM_X4(alr, aa + A_TILE);
                #pragma unroll
                for (int nt = 0; nt < 4; nt++) {
                    MMA_BF16(acc[mt][nt], ah,  bh[nt]);
                    MMA_BF16(acc[mt][nt], ah,  bl[nt]);
                    MMA_BF16(acc[mt][nt], alr, bh[nt]);
                }
            }
        }
        if (c + 1 < NCHUNK) { stsA(c + 1, db ^ 1); CP_WAIT0(); }
        __syncthreads();
    }

    // ---- epilogue ----
    float* Cp = (Ccode == 0) ? g_H : (Ccode == 1) ? g_Y : outp;
    const int rbase = warpM * 64 + (lane >> 2);
    const int cbase = n0 + warpN * 32 + (lane & 3) * 2;
    #pragma unroll
    for (int mt = 0; mt < 4; mt++) {
        #pragma unroll
        for (int rh = 0; rh < 2; rh++) {
            int lr = rbase + mt * 16 + rh * 8;
            int grow = m0 + lr;
            if (grow >= Nrows) continue;
            float* cp = Cp + (size_t)grow * F_DIM + cbase;
            float sc = 0.f; const float* vp = 0;
            if (accmode == 2) { sc = sRsc[lr]; vp = g_vmol + (size_t)sRm[lr] * F_DIM + cbase; }
            #pragma unroll
            for (int nt = 0; nt < 4; nt++) {
                float v0 = acc[mt][nt][rh * 2 + 0];
                float v1 = acc[mt][nt][rh * 2 + 1];
                float* dst = cp + nt * 8;
                if (accmode == 1) {
                    float2 o = *(float2*)dst;
                    v0 += o.x; v1 += o.y;
                } else if (accmode == 2) {
                    float2 o = *(const float2*)(vp + nt * 8);
                    v0 += sc * o.x; v1 += sc * o.y;
                }
                *(float2*)dst = make_float2(v0, v1);
            }
        }
    }
}

// ============================================================
extern "C" void kernel_launch(void* const* d_in, const int* in_sizes, int n_in,
                              void* d_out, int out_size) {
    const float* x    = (const float*)d_in[0];
    const float* E    = (const float*)d_in[1];
    const int*   asi  = (const int*)  d_in[2];
    const float* Wq   = (const float*)d_in[3];
    const float* bq   = (const float*)d_in[4];
    const float* Wk   = (const float*)d_in[5];
    const float* Wv   = (const float*)d_in[6];
    const float* W1   = (const float*)d_in[7];
    const float* W2   = (const float*)d_in[8];
    const float* a1   = (const float*)d_in[9];
    const float* b1   = (const float*)d_in[10];
    const float* a2   = (const float*)d_in[11];
    const float* b2   = (const float*)d_in[12];
    const float* oa   = (const float*)d_in[13];
    const float* ob   = (const float*)d_in[14];
    const float* Wout = (const float*)d_in[15];

    int B = in_sizes[1];
    int N = in_sizes[2];
    int R = in_sizes[7] / (F_DIM * F_DIM);
    float* out = (float*)d_out;

    cudaFuncSetAttribute(gemm_tc, cudaFuncAttributeMaxDynamicSharedMemorySize, SM_TOTAL);

    mol_prep<<<(B + 15) / 16, 256>>>(E, Wq, bq, Wk, Wv, B);          // 0

    int gS = (N + 7) / 8;
    atom_score<<<gS, 256>>>(x, asi, N);                               // 1

    int wblocks = ((2 * R + 1) * F_DIM * F_DIM + 255) / 256;
    prep_misc<<<1 + wblocks, 256>>>(W1, W2, Wout, R, gS);             // 2

    dim3 grid((N + 127) / 128, 2);
    // stage 0: virtual-h -> Y                                           3
    gemm_tc<<<grid, 256, SM_TOTAL>>>(3, 0, a1, b1, 1, 0, out, asi, N);
    // stage 1: Y -> H (= gather_h + acc)                                4
    gemm_tc<<<grid, 256, SM_TOTAL>>>(1, 1, a2, b2, 0, 2, out, asi, N);
    for (int i = 1; i < R; i++) {                                     // 5, 6 (ncu -s 5 -> launch 5)
        gemm_tc<<<grid, 256, SM_TOTAL>>>(0, 2 * i,     a1 + i * F_DIM, b1 + i * F_DIM, 1, 0, out, asi, N);
        gemm_tc<<<grid, 256, SM_TOTAL>>>(1, 2 * i + 1, a2 + i * F_DIM, b2 + i * F_DIM, 0, 1, out, asi, N);
    }
    gemm_tc<<<grid, 256, SM_TOTAL>>>(0, 2 * R, oa, ob, 2, 0, out, asi, N);
}